// round 1
// baseline (speedup 1.0000x reference)
#include <cuda_runtime.h>
#include <math.h>
#include <stdint.h>

// ---------------------------------------------------------------------------
// Scratch (static __device__ — no allocations allowed)
// ---------------------------------------------------------------------------
__device__ float g_Q[7340032];              // max B*N*Cc = 4*4096*448
__device__ float g_K[7340032];
__device__ float g_S[67108864];             // max B*N*N = 4*4096*4096 (268MB)
__device__ float g_mu_c[8192], g_rs_c[8192];
__device__ float g_mu_q[8192], g_rs_q[8192];
__device__ float g_mu_k[8192], g_rs_k[8192];
__device__ float g_part[2048];              // per-block partial sums (deterministic)

// ---------------------------------------------------------------------------
// Instance-norm stats: mean + rsqrt(var+1e-5) per (b, channel), reduced over N.
// grid: (C/32, B), block 256 = 32 channel lanes x 8 row lanes.
// ---------------------------------------------------------------------------
__global__ void stats_kernel(const float* __restrict__ x, float* __restrict__ mu,
                             float* __restrict__ rs, int N, int C) {
    int b = blockIdx.y;
    int lane = threadIdx.x & 31;
    int rl = threadIdx.x >> 5;               // 0..7
    int ch = blockIdx.x * 32 + lane;
    const float* p = x + (size_t)b * N * C + ch;
    float s = 0.f, s2 = 0.f;
    for (int n = rl; n < N; n += 8) {
        float v = p[(size_t)n * C];
        s += v; s2 += v * v;
    }
    __shared__ float shs[8][32];
    __shared__ float shq[8][32];
    shs[rl][lane] = s;
    shq[rl][lane] = s2;
    __syncthreads();
    if (rl == 0) {
        #pragma unroll
        for (int r = 1; r < 8; r++) { s += shs[r][lane]; s2 += shq[r][lane]; }
        float m = s / (float)N;
        float var = s2 / (float)N - m * m;
        mu[b * C + ch] = m;
        rs[b * C + ch] = rsqrtf(var + 1e-5f);
    }
}

// ---------------------------------------------------------------------------
// Elementwise normalize: out = (x - mu) * rs   (per b,channel)
// ---------------------------------------------------------------------------
__global__ void norm_kernel(const float* __restrict__ x, const float* __restrict__ mu,
                            const float* __restrict__ rs, float* __restrict__ out,
                            int NC, int C, size_t total) {
    size_t idx = (size_t)blockIdx.x * blockDim.x + threadIdx.x;
    if (idx >= total) return;
    int ch = (int)(idx % C);
    int b  = (int)(idx / NC);
    out[idx] = (x[idx] - mu[b * C + ch]) * rs[b * C + ch];
}

// ---------------------------------------------------------------------------
// S[b] = Q[b] (NxKc) @ K[b]^T (KcxN).  64x64 tile, 4x4 microtile, KT=16.
// grid: (N/64, N/64, B), block 256.
// ---------------------------------------------------------------------------
__global__ void __launch_bounds__(256) gemm_qk(const float* __restrict__ Q,
                                               const float* __restrict__ K,
                                               float* __restrict__ S, int N, int Kc) {
    __shared__ float Qs[16][68];
    __shared__ float Ks[16][68];
    int b = blockIdx.z;
    const float* Qb = Q + (size_t)b * N * Kc;
    const float* Kb = K + (size_t)b * N * Kc;
    float* Sb = S + (size_t)b * N * N;
    int i0 = blockIdx.y << 6, j0 = blockIdx.x << 6;
    int tid = threadIdx.x;
    int tr = tid >> 4, tc = tid & 15;
    int lr = tid >> 2;                 // 0..63
    int lk = (tid & 3) << 2;           // 0,4,8,12
    const float* qp = Qb + (size_t)(i0 + lr) * Kc + lk;
    const float* kp = Kb + (size_t)(j0 + lr) * Kc + lk;
    float acc[4][4] = {{0.f}};
    for (int k0 = 0; k0 < Kc; k0 += 16) {
        float4 q4 = *(const float4*)(qp + k0);
        float4 k4 = *(const float4*)(kp + k0);
        Qs[lk + 0][lr] = q4.x; Qs[lk + 1][lr] = q4.y;
        Qs[lk + 2][lr] = q4.z; Qs[lk + 3][lr] = q4.w;
        Ks[lk + 0][lr] = k4.x; Ks[lk + 1][lr] = k4.y;
        Ks[lk + 2][lr] = k4.z; Ks[lk + 3][lr] = k4.w;
        __syncthreads();
        #pragma unroll
        for (int kk = 0; kk < 16; kk++) {
            float a0 = Qs[kk][tr * 4 + 0], a1 = Qs[kk][tr * 4 + 1];
            float a2 = Qs[kk][tr * 4 + 2], a3 = Qs[kk][tr * 4 + 3];
            float b0 = Ks[kk][tc * 4 + 0], b1 = Ks[kk][tc * 4 + 1];
            float b2 = Ks[kk][tc * 4 + 2], b3 = Ks[kk][tc * 4 + 3];
            acc[0][0] += a0 * b0; acc[0][1] += a0 * b1; acc[0][2] += a0 * b2; acc[0][3] += a0 * b3;
            acc[1][0] += a1 * b0; acc[1][1] += a1 * b1; acc[1][2] += a1 * b2; acc[1][3] += a1 * b3;
            acc[2][0] += a2 * b0; acc[2][1] += a2 * b1; acc[2][2] += a2 * b2; acc[2][3] += a2 * b3;
            acc[3][0] += a3 * b0; acc[3][1] += a3 * b1; acc[3][2] += a3 * b2; acc[3][3] += a3 * b3;
        }
        __syncthreads();
    }
    #pragma unroll
    for (int ii = 0; ii < 4; ii++) {
        float4 o = make_float4(acc[ii][0], acc[ii][1], acc[ii][2], acc[ii][3]);
        *(float4*)(Sb + (size_t)(i0 + tr * 4 + ii) * N + j0 + tc * 4) = o;
    }
}

// ---------------------------------------------------------------------------
// Row softmax in place. One block per row; row cached in smem.
// ---------------------------------------------------------------------------
template <int N>
__global__ void softmax_kernel(float* __restrict__ S) {
    __shared__ float row[N];
    __shared__ float red[256];
    int b = blockIdx.y;
    float* r = S + ((size_t)b * N + blockIdx.x) * (size_t)N;
    int tid = threadIdx.x;
    float lmax = -1e30f;
    for (int m = tid; m < N; m += 256) {
        float v = r[m];
        row[m] = v;
        lmax = fmaxf(lmax, v);
    }
    red[tid] = lmax; __syncthreads();
    #pragma unroll
    for (int s = 128; s > 0; s >>= 1) {
        if (tid < s) red[tid] = fmaxf(red[tid], red[tid + s]);
        __syncthreads();
    }
    float gmax = red[0];
    __syncthreads();
    float lsum = 0.f;
    for (int m = tid; m < N; m += 256) {
        float e = expf(row[m] - gmax);
        row[m] = e;
        lsum += e;
    }
    red[tid] = lsum; __syncthreads();
    #pragma unroll
    for (int s = 128; s > 0; s >>= 1) {
        if (tid < s) red[tid] += red[tid + s];
        __syncthreads();
    }
    float inv = 1.f / red[0];
    for (int m = tid; m < N; m += 256) r[m] = row[m] * inv;
}

// ---------------------------------------------------------------------------
// Fused M = A@V, EV2 = A@(V*V), epilogue: S2=EV2-M^2, S=sqrt(max(max(S2,0),1e-9)),
// nc=(c-mu)*rs, err=(cs-(S*nc+M))^2, per-block partial -> g_part (deterministic).
// grid: (C/64, N/64, B), block 256.
// ---------------------------------------------------------------------------
__global__ void __launch_bounds__(256) gemm_av(const float* __restrict__ A,
                                               const float* __restrict__ V,
                                               const float* __restrict__ cs,
                                               const float* __restrict__ cin,
                                               const float* __restrict__ mu,
                                               const float* __restrict__ rs,
                                               float* __restrict__ part,
                                               int N, int C, int partBase) {
    __shared__ float As[16][68];
    __shared__ float Vs[16][64];
    __shared__ float V2s[16][64];
    int b = blockIdx.z;
    const float* Ab = A + (size_t)b * N * N;
    const float* Vb = V + (size_t)b * N * C;
    int i0 = blockIdx.y << 6, c0 = blockIdx.x << 6;
    int tid = threadIdx.x;
    int tr = tid >> 4, tc = tid & 15;
    int lr = tid >> 2, lk = (tid & 3) << 2;
    int vr = tid >> 4, vc = (tid & 15) << 2;
    float accM[4][4] = {{0.f}}, accS[4][4] = {{0.f}};
    for (int m0 = 0; m0 < N; m0 += 16) {
        float4 a4 = *(const float4*)(Ab + (size_t)(i0 + lr) * N + m0 + lk);
        As[lk + 0][lr] = a4.x; As[lk + 1][lr] = a4.y;
        As[lk + 2][lr] = a4.z; As[lk + 3][lr] = a4.w;
        float4 v4 = *(const float4*)(Vb + (size_t)(m0 + vr) * C + c0 + vc);
        *(float4*)&Vs[vr][vc]  = v4;
        *(float4*)&V2s[vr][vc] = make_float4(v4.x * v4.x, v4.y * v4.y,
                                             v4.z * v4.z, v4.w * v4.w);
        __syncthreads();
        #pragma unroll
        for (int kk = 0; kk < 16; kk++) {
            float a0 = As[kk][tr * 4 + 0], a1 = As[kk][tr * 4 + 1];
            float a2 = As[kk][tr * 4 + 2], a3 = As[kk][tr * 4 + 3];
            #pragma unroll
            for (int jj = 0; jj < 4; jj++) {
                float v  = Vs[kk][tc * 4 + jj];
                float v2 = V2s[kk][tc * 4 + jj];
                accM[0][jj] += a0 * v;  accS[0][jj] += a0 * v2;
                accM[1][jj] += a1 * v;  accS[1][jj] += a1 * v2;
                accM[2][jj] += a2 * v;  accS[2][jj] += a2 * v2;
                accM[3][jj] += a3 * v;  accS[3][jj] += a3 * v2;
            }
        }
        __syncthreads();
    }
    float local = 0.f;
    #pragma unroll
    for (int ii = 0; ii < 4; ii++) {
        int i = i0 + tr * 4 + ii;
        #pragma unroll
        for (int jj = 0; jj < 4; jj++) {
            int ch = c0 + tc * 4 + jj;
            float M  = accM[ii][jj];
            float S2 = accS[ii][jj] - M * M;
            float Sd = sqrtf(fmaxf(fmaxf(S2, 0.f), 1e-9f));
            size_t idx = ((size_t)b * N + i) * C + ch;
            float nc = (cin[idx] - mu[b * C + ch]) * rs[b * C + ch];
            float e  = cs[idx] - (Sd * nc + M);
            local += e * e;
        }
    }
    __shared__ float red[256];
    red[tid] = local; __syncthreads();
    #pragma unroll
    for (int s = 128; s > 0; s >>= 1) {
        if (tid < s) red[tid] += red[tid + s];
        __syncthreads();
    }
    if (tid == 0) {
        int bid = (blockIdx.z * gridDim.y + blockIdx.y) * gridDim.x + blockIdx.x;
        part[partBase + bid] = red[0];
    }
}

// ---------------------------------------------------------------------------
// Final deterministic reduction of partials -> scalar loss.
// ---------------------------------------------------------------------------
__global__ void final_kernel(const float* __restrict__ part, float* __restrict__ out) {
    __shared__ float red[256];
    __shared__ float lossAcc;
    int tid = threadIdx.x;
    const int bases[3]  = {0, 1024, 1536};
    const int counts[3] = {1024, 512, 128};
    const float inv[3]  = {1.f / 4194304.f, 1.f / 2097152.f, 1.f / 524288.f};
    if (tid == 0) lossAcc = 0.f;
    __syncthreads();
    for (int sc = 0; sc < 3; sc++) {
        float s = 0.f;
        for (int i = tid; i < counts[sc]; i += 256) s += part[bases[sc] + i];
        red[tid] = s; __syncthreads();
        #pragma unroll
        for (int st = 128; st > 0; st >>= 1) {
            if (tid < st) red[tid] += red[tid + st];
            __syncthreads();
        }
        if (tid == 0) lossAcc += red[0] * inv[sc];
        __syncthreads();
    }
    if (tid == 0) out[0] = lossAcc;
}

// ---------------------------------------------------------------------------
// Host side
// ---------------------------------------------------------------------------
static void run_scale(const float* cs, const float* cin, const float* sty,
                      const float* cc, const float* sc,
                      int N, int C, int Cc,
                      float* Q, float* K, float* S,
                      float* muc, float* rsc, float* muq, float* rsq,
                      float* muk, float* rsk,
                      float* part, int partBase) {
    dim3 stc(C / 32, 4);
    dim3 stq(Cc / 32, 4);
    stats_kernel<<<stc, 256>>>(cin, muc, rsc, N, C);
    stats_kernel<<<stq, 256>>>(cc, muq, rsq, N, Cc);
    stats_kernel<<<stq, 256>>>(sc, muk, rsk, N, Cc);

    size_t tot = (size_t)4 * N * Cc;
    int nb = (int)((tot + 255) / 256);
    norm_kernel<<<nb, 256>>>(cc, muq, rsq, Q, N * Cc, Cc, tot);
    norm_kernel<<<nb, 256>>>(sc, muk, rsk, K, N * Cc, Cc, tot);

    dim3 g1(N / 64, N / 64, 4);
    gemm_qk<<<g1, 256>>>(Q, K, S, N, Cc);

    dim3 g2(N, 4);
    if (N == 4096)      softmax_kernel<4096><<<g2, 256>>>(S);
    else if (N == 1024) softmax_kernel<1024><<<g2, 256>>>(S);
    else                softmax_kernel<256><<<g2, 256>>>(S);

    dim3 g3(C / 64, N / 64, 4);
    gemm_av<<<g3, 256>>>(S, sty, cs, cin, muc, rsc, part, N, C, partBase);
}

extern "C" void kernel_launch(void* const* d_in, const int* in_sizes, int n_in,
                              void* d_out, int out_size) {
    float *Q, *K, *S, *muc, *rsc, *muq, *rsq, *muk, *rsk, *part;
    cudaGetSymbolAddress((void**)&Q,   g_Q);
    cudaGetSymbolAddress((void**)&K,   g_K);
    cudaGetSymbolAddress((void**)&S,   g_S);
    cudaGetSymbolAddress((void**)&muc, g_mu_c);
    cudaGetSymbolAddress((void**)&rsc, g_rs_c);
    cudaGetSymbolAddress((void**)&muq, g_mu_q);
    cudaGetSymbolAddress((void**)&rsq, g_rs_q);
    cudaGetSymbolAddress((void**)&muk, g_mu_k);
    cudaGetSymbolAddress((void**)&rsk, g_rs_k);
    cudaGetSymbolAddress((void**)&part, g_part);

    // inputs: cs2,c2,s2,cc2,sc2, cs3,c3,s3,cc3,sc3, cs4,c4,s4,cc4,sc4
    run_scale((const float*)d_in[0], (const float*)d_in[1], (const float*)d_in[2],
              (const float*)d_in[3], (const float*)d_in[4],
              4096, 256, 448, Q, K, S, muc, rsc, muq, rsq, muk, rsk, part, 0);
    run_scale((const float*)d_in[5], (const float*)d_in[6], (const float*)d_in[7],
              (const float*)d_in[8], (const float*)d_in[9],
              1024, 512, 960, Q, K, S, muc, rsc, muq, rsq, muk, rsk, part, 1024);
    run_scale((const float*)d_in[10], (const float*)d_in[11], (const float*)d_in[12],
              (const float*)d_in[13], (const float*)d_in[14],
              256, 512, 1472, Q, K, S, muc, rsc, muq, rsq, muk, rsk, part, 1536);

    final_kernel<<<1, 256>>>(part, (float*)d_out);
}

// round 2
// speedup vs baseline: 1.0535x; 1.0535x over previous
#include <cuda_runtime.h>
#include <math.h>
#include <stdint.h>

// ---------------------------------------------------------------------------
// Scratch (static __device__ — no allocations allowed)
// ---------------------------------------------------------------------------
__device__ float g_Q[7340032];              // max B*N*Cc = 4*4096*448
__device__ float g_K[7340032];
__device__ float g_S[67108864];             // max B*N*N = 4*4096*4096 (268MB)
__device__ float g_mu_c[8192], g_rs_c[8192];
__device__ float g_mu_q[8192], g_rs_q[8192];
__device__ float g_mu_k[8192], g_rs_k[8192];
__device__ float g_part[2048];              // per-block partial sums (deterministic)

// ---------------------------------------------------------------------------
// Instance-norm stats: mean + rsqrt(var+1e-5) per (b, channel), reduced over N.
// grid: (C/32, B), block 256 = 32 channel lanes x 8 row lanes.
// ---------------------------------------------------------------------------
__global__ void stats_kernel(const float* __restrict__ x, float* __restrict__ mu,
                             float* __restrict__ rs, int N, int C) {
    int b = blockIdx.y;
    int lane = threadIdx.x & 31;
    int rl = threadIdx.x >> 5;               // 0..7
    int ch = blockIdx.x * 32 + lane;
    const float* p = x + (size_t)b * N * C + ch;
    float s = 0.f, s2 = 0.f;
    for (int n = rl; n < N; n += 8) {
        float v = p[(size_t)n * C];
        s += v; s2 += v * v;
    }
    __shared__ float shs[8][32];
    __shared__ float shq[8][32];
    shs[rl][lane] = s;
    shq[rl][lane] = s2;
    __syncthreads();
    if (rl == 0) {
        #pragma unroll
        for (int r = 1; r < 8; r++) { s += shs[r][lane]; s2 += shq[r][lane]; }
        float m = s / (float)N;
        float var = s2 / (float)N - m * m;
        mu[b * C + ch] = m;
        rs[b * C + ch] = rsqrtf(var + 1e-5f);
    }
}

// ---------------------------------------------------------------------------
// Elementwise normalize: out = (x - mu) * rs   (per b,channel)
// ---------------------------------------------------------------------------
__global__ void norm_kernel(const float* __restrict__ x, const float* __restrict__ mu,
                            const float* __restrict__ rs, float* __restrict__ out,
                            int NC, int C, size_t total) {
    size_t idx = (size_t)blockIdx.x * blockDim.x + threadIdx.x;
    if (idx >= total) return;
    int ch = (int)(idx % C);
    int b  = (int)(idx / NC);
    out[idx] = (x[idx] - mu[b * C + ch]) * rs[b * C + ch];
}

// ---------------------------------------------------------------------------
// S[b] = Q[b] (NxKc) @ K[b]^T (KcxN).  64x64 tile, 4x4 microtile, KT=16.
// grid: (N/64, N/64, B), block 256.
// ---------------------------------------------------------------------------
__global__ void __launch_bounds__(256) gemm_qk(const float* __restrict__ Q,
                                               const float* __restrict__ K,
                                               float* __restrict__ S, int N, int Kc) {
    __shared__ float Qs[16][68];
    __shared__ float Ks[16][68];
    int b = blockIdx.z;
    const float* Qb = Q + (size_t)b * N * Kc;
    const float* Kb = K + (size_t)b * N * Kc;
    float* Sb = S + (size_t)b * N * N;
    int i0 = blockIdx.y << 6, j0 = blockIdx.x << 6;
    int tid = threadIdx.x;
    int tr = tid >> 4, tc = tid & 15;
    int lr = tid >> 2;                 // 0..63
    int lk = (tid & 3) << 2;           // 0,4,8,12
    const float* qp = Qb + (size_t)(i0 + lr) * Kc + lk;
    const float* kp = Kb + (size_t)(j0 + lr) * Kc + lk;
    float acc[4][4] = {{0.f}};
    for (int k0 = 0; k0 < Kc; k0 += 16) {
        float4 q4 = *(const float4*)(qp + k0);
        float4 k4 = *(const float4*)(kp + k0);
        Qs[lk + 0][lr] = q4.x; Qs[lk + 1][lr] = q4.y;
        Qs[lk + 2][lr] = q4.z; Qs[lk + 3][lr] = q4.w;
        Ks[lk + 0][lr] = k4.x; Ks[lk + 1][lr] = k4.y;
        Ks[lk + 2][lr] = k4.z; Ks[lk + 3][lr] = k4.w;
        __syncthreads();
        #pragma unroll
        for (int kk = 0; kk < 16; kk++) {
            float a0 = Qs[kk][tr * 4 + 0], a1 = Qs[kk][tr * 4 + 1];
            float a2 = Qs[kk][tr * 4 + 2], a3 = Qs[kk][tr * 4 + 3];
            float b0 = Ks[kk][tc * 4 + 0], b1 = Ks[kk][tc * 4 + 1];
            float b2 = Ks[kk][tc * 4 + 2], b3 = Ks[kk][tc * 4 + 3];
            acc[0][0] += a0 * b0; acc[0][1] += a0 * b1; acc[0][2] += a0 * b2; acc[0][3] += a0 * b3;
            acc[1][0] += a1 * b0; acc[1][1] += a1 * b1; acc[1][2] += a1 * b2; acc[1][3] += a1 * b3;
            acc[2][0] += a2 * b0; acc[2][1] += a2 * b1; acc[2][2] += a2 * b2; acc[2][3] += a2 * b3;
            acc[3][0] += a3 * b0; acc[3][1] += a3 * b1; acc[3][2] += a3 * b2; acc[3][3] += a3 * b3;
        }
        __syncthreads();
    }
    #pragma unroll
    for (int ii = 0; ii < 4; ii++) {
        float4 o = make_float4(acc[ii][0], acc[ii][1], acc[ii][2], acc[ii][3]);
        *(float4*)(Sb + (size_t)(i0 + tr * 4 + ii) * N + j0 + tc * 4) = o;
    }
}

// ---------------------------------------------------------------------------
// Row softmax in place. One block per row; row cached in smem.
// ---------------------------------------------------------------------------
template <int N>
__global__ void softmax_kernel(float* __restrict__ S) {
    __shared__ float row[N];
    __shared__ float red[256];
    int b = blockIdx.y;
    float* r = S + ((size_t)b * N + blockIdx.x) * (size_t)N;
    int tid = threadIdx.x;
    float lmax = -1e30f;
    for (int m = tid; m < N; m += 256) {
        float v = r[m];
        row[m] = v;
        lmax = fmaxf(lmax, v);
    }
    red[tid] = lmax; __syncthreads();
    #pragma unroll
    for (int s = 128; s > 0; s >>= 1) {
        if (tid < s) red[tid] = fmaxf(red[tid], red[tid + s]);
        __syncthreads();
    }
    float gmax = red[0];
    __syncthreads();
    float lsum = 0.f;
    for (int m = tid; m < N; m += 256) {
        float e = expf(row[m] - gmax);
        row[m] = e;
        lsum += e;
    }
    red[tid] = lsum; __syncthreads();
    #pragma unroll
    for (int s = 128; s > 0; s >>= 1) {
        if (tid < s) red[tid] += red[tid + s];
        __syncthreads();
    }
    float inv = 1.f / red[0];
    for (int m = tid; m < N; m += 256) r[m] = row[m] * inv;
}

// ---------------------------------------------------------------------------
// Fused M = A@V, EV2 = A@(V*V), epilogue: S2=EV2-M^2, S=sqrt(max(max(S2,0),1e-9)),
// nc=(c-mu)*rs, err=(cs-(S*nc+M))^2, per-block partial -> g_part (deterministic).
// grid: (C/64, N/64, B), block 256.
// ---------------------------------------------------------------------------
__global__ void __launch_bounds__(256) gemm_av(const float* __restrict__ A,
                                               const float* __restrict__ V,
                                               const float* __restrict__ cs,
                                               const float* __restrict__ cin,
                                               const float* __restrict__ mu,
                                               const float* __restrict__ rs,
                                               float* __restrict__ part,
                                               int N, int C, int partBase) {
    __shared__ float As[16][68];
    __shared__ float Vs[16][64];
    __shared__ float V2s[16][64];
    int b = blockIdx.z;
    const float* Ab = A + (size_t)b * N * N;
    const float* Vb = V + (size_t)b * N * C;
    int i0 = blockIdx.y << 6, c0 = blockIdx.x << 6;
    int tid = threadIdx.x;
    int tr = tid >> 4, tc = tid & 15;
    int lr = tid >> 2, lk = (tid & 3) << 2;
    int vr = tid >> 4, vc = (tid & 15) << 2;
    float accM[4][4] = {{0.f}}, accS[4][4] = {{0.f}};
    for (int m0 = 0; m0 < N; m0 += 16) {
        float4 a4 = *(const float4*)(Ab + (size_t)(i0 + lr) * N + m0 + lk);
        As[lk + 0][lr] = a4.x; As[lk + 1][lr] = a4.y;
        As[lk + 2][lr] = a4.z; As[lk + 3][lr] = a4.w;
        float4 v4 = *(const float4*)(Vb + (size_t)(m0 + vr) * C + c0 + vc);
        *(float4*)&Vs[vr][vc]  = v4;
        *(float4*)&V2s[vr][vc] = make_float4(v4.x * v4.x, v4.y * v4.y,
                                             v4.z * v4.z, v4.w * v4.w);
        __syncthreads();
        #pragma unroll
        for (int kk = 0; kk < 16; kk++) {
            float a0 = As[kk][tr * 4 + 0], a1 = As[kk][tr * 4 + 1];
            float a2 = As[kk][tr * 4 + 2], a3 = As[kk][tr * 4 + 3];
            #pragma unroll
            for (int jj = 0; jj < 4; jj++) {
                float v  = Vs[kk][tc * 4 + jj];
                float v2 = V2s[kk][tc * 4 + jj];
                accM[0][jj] += a0 * v;  accS[0][jj] += a0 * v2;
                accM[1][jj] += a1 * v;  accS[1][jj] += a1 * v2;
                accM[2][jj] += a2 * v;  accS[2][jj] += a2 * v2;
                accM[3][jj] += a3 * v;  accS[3][jj] += a3 * v2;
            }
        }
        __syncthreads();
    }
    float local = 0.f;
    #pragma unroll
    for (int ii = 0; ii < 4; ii++) {
        int i = i0 + tr * 4 + ii;
        #pragma unroll
        for (int jj = 0; jj < 4; jj++) {
            int ch = c0 + tc * 4 + jj;
            float M  = accM[ii][jj];
            float S2 = accS[ii][jj] - M * M;
            float Sd = sqrtf(fmaxf(fmaxf(S2, 0.f), 1e-9f));
            size_t idx = ((size_t)b * N + i) * C + ch;
            float nc = (cin[idx] - mu[b * C + ch]) * rs[b * C + ch];
            float e  = cs[idx] - (Sd * nc + M);
            local += e * e;
        }
    }
    __shared__ float red[256];
    red[tid] = local; __syncthreads();
    #pragma unroll
    for (int s = 128; s > 0; s >>= 1) {
        if (tid < s) red[tid] += red[tid + s];
        __syncthreads();
    }
    if (tid == 0) {
        int bid = (blockIdx.z * gridDim.y + blockIdx.y) * gridDim.x + blockIdx.x;
        part[partBase + bid] = red[0];
    }
}

// ---------------------------------------------------------------------------
// Final deterministic reduction of partials -> scalar loss.
// ---------------------------------------------------------------------------
__global__ void final_kernel(const float* __restrict__ part, float* __restrict__ out) {
    __shared__ float red[256];
    __shared__ float lossAcc;
    int tid = threadIdx.x;
    const int bases[3]  = {0, 1024, 1536};
    const int counts[3] = {1024, 512, 128};
    const float inv[3]  = {1.f / 4194304.f, 1.f / 2097152.f, 1.f / 524288.f};
    if (tid == 0) lossAcc = 0.f;
    __syncthreads();
    for (int sc = 0; sc < 3; sc++) {
        float s = 0.f;
        for (int i = tid; i < counts[sc]; i += 256) s += part[bases[sc] + i];
        red[tid] = s; __syncthreads();
        #pragma unroll
        for (int st = 128; st > 0; st >>= 1) {
            if (tid < st) red[tid] += red[tid + st];
            __syncthreads();
        }
        if (tid == 0) lossAcc += red[0] * inv[sc];
        __syncthreads();
    }
    if (tid == 0) out[0] = lossAcc;
}

// ---------------------------------------------------------------------------
// Host side
// ---------------------------------------------------------------------------
static void run_scale(const float* cs, const float* cin, const float* sty,
                      const float* cc, const float* sc,
                      int N, int C, int Cc,
                      float* Q, float* K, float* S,
                      float* muc, float* rsc, float* muq, float* rsq,
                      float* muk, float* rsk,
                      float* part, int partBase) {
    dim3 stc(C / 32, 4);
    dim3 stq(Cc / 32, 4);
    stats_kernel<<<stc, 256>>>(cin, muc, rsc, N, C);
    stats_kernel<<<stq, 256>>>(cc, muq, rsq, N, Cc);
    stats_kernel<<<stq, 256>>>(sc, muk, rsk, N, Cc);

    size_t tot = (size_t)4 * N * Cc;
    int nb = (int)((tot + 255) / 256);
    norm_kernel<<<nb, 256>>>(cc, muq, rsq, Q, N * Cc, Cc, tot);
    norm_kernel<<<nb, 256>>>(sc, muk, rsk, K, N * Cc, Cc, tot);

    dim3 g1(N / 64, N / 64, 4);
    gemm_qk<<<g1, 256>>>(Q, K, S, N, Cc);

    dim3 g2(N, 4);
    if (N == 4096)      softmax_kernel<4096><<<g2, 256>>>(S);
    else if (N == 1024) softmax_kernel<1024><<<g2, 256>>>(S);
    else                softmax_kernel<256><<<g2, 256>>>(S);

    dim3 g3(C / 64, N / 64, 4);
    gemm_av<<<g3, 256>>>(S, sty, cs, cin, muc, rsc, part, N, C, partBase);
}

extern "C" void kernel_launch(void* const* d_in, const int* in_sizes, int n_in,
                              void* d_out, int out_size) {
    float *Q, *K, *S, *muc, *rsc, *muq, *rsq, *muk, *rsk, *part;
    cudaGetSymbolAddress((void**)&Q,   g_Q);
    cudaGetSymbolAddress((void**)&K,   g_K);
    cudaGetSymbolAddress((void**)&S,   g_S);
    cudaGetSymbolAddress((void**)&muc, g_mu_c);
    cudaGetSymbolAddress((void**)&rsc, g_rs_c);
    cudaGetSymbolAddress((void**)&muq, g_mu_q);
    cudaGetSymbolAddress((void**)&rsq, g_rs_q);
    cudaGetSymbolAddress((void**)&muk, g_mu_k);
    cudaGetSymbolAddress((void**)&rsk, g_rs_k);
    cudaGetSymbolAddress((void**)&part, g_part);

    // inputs: cs2,c2,s2,cc2,sc2, cs3,c3,s3,cc3,sc3, cs4,c4,s4,cc4,sc4
    run_scale((const float*)d_in[0], (const float*)d_in[1], (const float*)d_in[2],
              (const float*)d_in[3], (const float*)d_in[4],
              4096, 256, 448, Q, K, S, muc, rsc, muq, rsq, muk, rsk, part, 0);
    run_scale((const float*)d_in[5], (const float*)d_in[6], (const float*)d_in[7],
              (const float*)d_in[8], (const float*)d_in[9],
              1024, 512, 960, Q, K, S, muc, rsc, muq, rsq, muk, rsk, part, 1024);
    run_scale((const float*)d_in[10], (const float*)d_in[11], (const float*)d_in[12],
              (const float*)d_in[13], (const float*)d_in[14],
              256, 512, 1472, Q, K, S, muc, rsc, muq, rsq, muk, rsk, part, 1536);

    final_kernel<<<1, 256>>>(part, (float*)d_out);
}

// round 4
// speedup vs baseline: 2.0746x; 1.9692x over previous
#include <cuda_runtime.h>
#include <cuda_bf16.h>
#include <math.h>
#include <stdint.h>
typedef __nv_bfloat16 bf16;

// ---------------- static scratch ----------------
__device__ bf16  g_Qe[14680064];   // B*N*(2*Cc) max
__device__ bf16  g_Ke[14680064];
__device__ float g_S[67108864];    // B*N*N fp32 scores
__device__ bf16  g_A[134217728];   // B*N*(2*N) hi|lo
__device__ bf16  g_W[16777216];    // B*(2C)*(2N), V/V^2 interleaved even/odd rows
__device__ float g_muc[8192], g_rsc[8192];
__device__ float g_muq[8192], g_rsq[8192];
__device__ float g_muk[8192], g_rsk[8192];
__device__ float g_part[1024];

// ---------------- PTX helpers (family-agnostic only!) ----------------
__device__ __forceinline__ uint32_t smem_u32(const void* p) {
    uint32_t a;
    asm("{ .reg .u64 t; cvta.to.shared.u64 t, %1; cvt.u32.u64 %0, t; }" : "=r"(a) : "l"(p));
    return a;
}
#define CP_ASYNC(dst, src) \
    asm volatile("cp.async.cg.shared.global [%0], [%1], 16;" :: "r"(dst), "l"(src))
#define CP_COMMIT() asm volatile("cp.async.commit_group;" ::: "memory")
#define CP_WAIT(n)  asm volatile("cp.async.wait_group %0;" :: "n"(n) : "memory")
#define LDSM4(r0, r1, r2, r3, addr) \
    asm volatile("ldmatrix.sync.aligned.m8n8.x4.shared.b16 {%0,%1,%2,%3}, [%4];" \
        : "=r"(r0), "=r"(r1), "=r"(r2), "=r"(r3) : "r"(addr))

__device__ __forceinline__ void mma16816(float* d, const uint32_t* a, const uint32_t* b) {
    asm volatile("mma.sync.aligned.m16n8k16.row.col.f32.bf16.bf16.f32 "
        "{%0,%1,%2,%3}, {%4,%5,%6,%7}, {%8,%9}, {%0,%1,%2,%3};"
        : "+f"(d[0]), "+f"(d[1]), "+f"(d[2]), "+f"(d[3])
        : "r"(a[0]), "r"(a[1]), "r"(a[2]), "r"(a[3]), "r"(b[0]), "r"(b[1]));
}

// ---------------- stats ----------------
__global__ void stats_kernel(const float* __restrict__ x, float* __restrict__ mu,
                             float* __restrict__ rs, int N, int C) {
    int b = blockIdx.y, lane = threadIdx.x & 31, rl = threadIdx.x >> 5;
    int ch = blockIdx.x * 32 + lane;
    const float* p = x + (size_t)b * N * C + ch;
    float s = 0.f, s2 = 0.f;
    for (int n = rl; n < N; n += 8) { float v = p[(size_t)n * C]; s += v; s2 += v * v; }
    __shared__ float shs[8][32], shq[8][32];
    shs[rl][lane] = s; shq[rl][lane] = s2;
    __syncthreads();
    if (rl == 0) {
        #pragma unroll
        for (int r = 1; r < 8; r++) { s += shs[r][lane]; s2 += shq[r][lane]; }
        float m = s / (float)N;
        mu[b * C + ch] = m;
        rs[b * C + ch] = rsqrtf(s2 / (float)N - m * m + 1e-5f);
    }
}

// ---------------- normalize + hi/lo split (Q/K) ----------------
__global__ void qk_prep(const float* __restrict__ x, const float* __restrict__ mu,
                        const float* __restrict__ rs, bf16* __restrict__ dst,
                        int N, int Cc) {
    size_t idx = (size_t)blockIdx.x * 256 + threadIdx.x;
    if (idx >= (size_t)4 * N * Cc) return;
    int ch = (int)(idx % Cc);
    size_t nrow = idx / Cc;
    int b = (int)(nrow / N);
    float v = (x[idx] - mu[b * Cc + ch]) * rs[b * Cc + ch];
    bf16 hi = __float2bfloat16(v);
    bf16* row = dst + nrow * (size_t)(2 * Cc);
    row[ch] = hi;
    row[Cc + ch] = __float2bfloat16(v - __bfloat162float(hi));
}

// ---------------- W: row 2*ch = V, row 2*ch+1 = V^2; each row [hi(N)|lo(N)] ----------------
__global__ void v_prep(const float* __restrict__ V, bf16* __restrict__ W, int N, int C) {
    __shared__ float t[32][33];
    int b = blockIdx.z, m0 = blockIdx.x * 32, ch0 = blockIdx.y * 32;
    int tx = threadIdx.x & 31, ty = threadIdx.x >> 5;
    const float* Vb = V + (size_t)b * N * C;
    #pragma unroll
    for (int k = 0; k < 4; k++)
        t[tx][ty + k * 8] = Vb[(size_t)(m0 + ty + k * 8) * C + ch0 + tx];
    __syncthreads();
    size_t rowLen = (size_t)2 * N;
    bf16* Wb = W + (size_t)b * 2 * C * rowLen;
    #pragma unroll
    for (int k = 0; k < 4; k++) {
        int j = ty + k * 8, ch = ch0 + j;
        float v = t[j][tx], v2 = v * v;
        bf16* rV = Wb + (size_t)(2 * ch) * rowLen;
        bf16* rQ = Wb + (size_t)(2 * ch + 1) * rowLen;
        int m = m0 + tx;
        bf16 h1 = __float2bfloat16(v);
        rV[m] = h1; rV[N + m] = __float2bfloat16(v - __bfloat162float(h1));
        bf16 h2 = __float2bfloat16(v2);
        rQ[m] = h2; rQ[N + m] = __float2bfloat16(v2 - __bfloat162float(h2));
    }
}

// ---------------- softmax: fp32 S -> bf16 hi|lo A ----------------
template <int N>
__global__ void softmax_kernel(const float* __restrict__ S, bf16* __restrict__ A) {
    __shared__ float row[N];
    __shared__ float red[256];
    int b = blockIdx.y, tid = threadIdx.x;
    const float* r = S + ((size_t)b * N + blockIdx.x) * (size_t)N;
    bf16* a = A + ((size_t)b * N + blockIdx.x) * (size_t)(2 * N);
    float lmax = -1e30f;
    for (int m = tid; m < N; m += 256) { float v = r[m]; row[m] = v; lmax = fmaxf(lmax, v); }
    red[tid] = lmax; __syncthreads();
    #pragma unroll
    for (int s = 128; s > 0; s >>= 1) { if (tid < s) red[tid] = fmaxf(red[tid], red[tid + s]); __syncthreads(); }
    float gmax = red[0]; __syncthreads();
    float lsum = 0.f;
    for (int m = tid; m < N; m += 256) { float e = __expf(row[m] - gmax); row[m] = e; lsum += e; }
    red[tid] = lsum; __syncthreads();
    #pragma unroll
    for (int s = 128; s > 0; s >>= 1) { if (tid < s) red[tid] += red[tid + s]; __syncthreads(); }
    float inv = 1.f / red[0];
    for (int m = tid; m < N; m += 256) {
        float v = row[m] * inv;
        bf16 hi = __float2bfloat16(v);
        a[m] = hi; a[N + m] = __float2bfloat16(v - __bfloat162float(hi));
    }
}

// ---------------------------------------------------------------------------
// HMMA GEMM: D[128x128] = X @ Y^T, bf16 hi/lo 3-pass, fp32 accum.
// X rows: [hi(Kdim)|lo(Kdim)], Y rows likewise. 8 warps: wm=wid>>1 (M 32-slab),
// wn=wid&1 (N 64-slab). Per warp: 2 m-tiles x 8 n-tiles of m16n8.
// mode 0: write fp32 scores. mode 1: V/V^2 even/odd-column pairing -> loss.
// ---------------------------------------------------------------------------
#define GSMEM 132096   // 2 stages * 64KB + 1KB reduce

__global__ void __launch_bounds__(256, 1) gemm_mma(
    const bf16* __restrict__ X, const bf16* __restrict__ Y,
    int Kdim, int mode, float* __restrict__ Sout,
    const float* __restrict__ cs, const float* __restrict__ cin,
    const float* __restrict__ mu, const float* __restrict__ rs,
    int C, int N, float* __restrict__ part, int partBase)
{
    extern __shared__ char sm[];
    uint32_t sb = smem_u32(sm);
    const int tid = threadIdx.x, wid = tid >> 5, lane = tid & 31;
    const int b = blockIdx.z;
    const int i0 = blockIdx.y * 128, j0 = blockIdx.x * 128;
    const int K2 = 2 * Kdim;
    const int Yrows = gridDim.x * 128;
    const bf16* Xb = X + (size_t)b * N * K2;
    const bf16* Yb = Y + (size_t)b * Yrows * K2;
    const int wm = wid >> 1, wn = wid & 1;

    float d[2][8][4];
    #pragma unroll
    for (int mt = 0; mt < 2; mt++)
        #pragma unroll
        for (int nt = 0; nt < 8; nt++)
            #pragma unroll
            for (int q = 0; q < 4; q++) d[mt][nt][q] = 0.f;

    const int NCH = Kdim / 64;

    auto issue_load = [&](int ch) {
        uint32_t stage = (uint32_t)(ch & 1) * 65536u;
        int kc = ch * 64;
        #pragma unroll
        for (int i = 0; i < 4; i++) {
            int idx = tid + i * 256;
            int r = idx >> 3, g = idx & 7;
            uint32_t dstoff = (uint32_t)(r * 128 + ((g * 16) ^ ((r & 7) << 4)));
            const bf16* x0 = Xb + (size_t)(i0 + r) * K2 + kc + g * 8;
            const bf16* y0 = Yb + (size_t)(j0 + r) * K2 + kc + g * 8;
            CP_ASYNC(sb + stage + dstoff,          x0);
            CP_ASYNC(sb + stage + 16384 + dstoff,  x0 + Kdim);
            CP_ASYNC(sb + stage + 32768 + dstoff,  y0);
            CP_ASYNC(sb + stage + 49152 + dstoff,  y0 + Kdim);
        }
        CP_COMMIT();
    };

    issue_load(0);
    for (int ch = 0; ch < NCH; ch++) {
        if (ch + 1 < NCH) { issue_load(ch + 1); CP_WAIT(1); }
        else              { CP_WAIT(0); }
        __syncthreads();
        uint32_t stage = sb + (uint32_t)(ch & 1) * 65536u;
        #pragma unroll
        for (int p = 0; p < 3; p++) {
            uint32_t Abase = stage + (p == 2 ? 16384u : 0u);
            uint32_t Bbase = stage + 32768u + (p == 1 ? 16384u : 0u);
            #pragma unroll
            for (int ks = 0; ks < 4; ks++) {
                int colb = ks * 32 + ((lane >> 4) << 4);
                uint32_t a[2][4];
                #pragma unroll
                for (int mt = 0; mt < 2; mt++) {
                    int row = wm * 32 + mt * 16 + (lane & 15);
                    LDSM4(a[mt][0], a[mt][1], a[mt][2], a[mt][3],
                          Abase + (uint32_t)(row * 128 + (colb ^ ((row & 7) << 4))));
                }
                #pragma unroll
                for (int ng = 0; ng < 4; ng++) {
                    uint32_t bb[4];
                    int row = wn * 64 + ng * 16 + (lane & 15);
                    LDSM4(bb[0], bb[1], bb[2], bb[3],
                          Bbase + (uint32_t)(row * 128 + (colb ^ ((row & 7) << 4))));
                    uint32_t be[2] = { bb[0], bb[2] };
                    uint32_t bo[2] = { bb[1], bb[3] };
                    #pragma unroll
                    for (int mt = 0; mt < 2; mt++) {
                        mma16816(d[mt][ng * 2],     a[mt], be);
                        mma16816(d[mt][ng * 2 + 1], a[mt], bo);
                    }
                }
            }
        }
        __syncthreads();
    }

    if (mode == 0) {
        #pragma unroll
        for (int mt = 0; mt < 2; mt++) {
            int r = i0 + wm * 32 + mt * 16 + (lane >> 2);
            #pragma unroll
            for (int nt = 0; nt < 8; nt++) {
                int c = j0 + wn * 64 + nt * 8 + (lane & 3) * 2;
                *(float2*)(Sout + ((size_t)b * N + r) * N + c) =
                    make_float2(d[mt][nt][0], d[mt][nt][1]);
                *(float2*)(Sout + ((size_t)b * N + r + 8) * N + c) =
                    make_float2(d[mt][nt][2], d[mt][nt][3]);
            }
        }
    } else {
        float local = 0.f;
        #pragma unroll
        for (int mt = 0; mt < 2; mt++) {
            int r = i0 + wm * 32 + mt * 16 + (lane >> 2);
            #pragma unroll
            for (int nt = 0; nt < 8; nt++) {
                int chn = ((j0 + wn * 64 + nt * 8) >> 1) + (lane & 3);
                #pragma unroll
                for (int h = 0; h < 2; h++) {
                    int i = r + h * 8;
                    float M = d[mt][nt][h * 2];
                    float S2 = d[mt][nt][h * 2 + 1] - M * M;
                    float Sd = sqrtf(fmaxf(fmaxf(S2, 0.f), 1e-9f));
                    size_t idx = ((size_t)b * N + i) * C + chn;
                    float nc = (cin[idx] - mu[b * C + chn]) * rs[b * C + chn];
                    float e = cs[idx] - (Sd * nc + M);
                    local += e * e;
                }
            }
        }
        float* red = (float*)sm;
        red[tid] = local; __syncthreads();
        #pragma unroll
        for (int s = 128; s > 0; s >>= 1) {
            if (tid < s) red[tid] += red[tid + s];
            __syncthreads();
        }
        if (tid == 0) {
            int bid = (blockIdx.z * gridDim.y + blockIdx.y) * gridDim.x + blockIdx.x;
            part[partBase + bid] = red[0];
        }
    }
}

// ---------------- final reduction ----------------
__global__ void final_kernel(const float* __restrict__ part, float* __restrict__ out) {
    __shared__ float red[256];
    __shared__ float acc;
    int tid = threadIdx.x;
    const int bases[3] = {0, 512, 768};
    const int counts[3] = {512, 256, 64};
    const float inv[3] = {1.f / 4194304.f, 1.f / 2097152.f, 1.f / 524288.f};
    if (tid == 0) acc = 0.f;
    __syncthreads();
    for (int sc = 0; sc < 3; sc++) {
        float s = 0.f;
        for (int i = tid; i < counts[sc]; i += 256) s += part[bases[sc] + i];
        red[tid] = s; __syncthreads();
        #pragma unroll
        for (int st = 128; st > 0; st >>= 1) { if (tid < st) red[tid] += red[tid + st]; __syncthreads(); }
        if (tid == 0) acc += red[0] * inv[sc];
        __syncthreads();
    }
    if (tid == 0) out[0] = acc;
}

// ---------------- host ----------------
static void run_scale(const float* cs, const float* cin, const float* sty,
                      const float* cc, const float* sc, int N, int C, int Cc,
                      bf16* Q, bf16* K, float* S, bf16* A, bf16* W,
                      float* muc, float* rsc, float* muq, float* rsq,
                      float* muk, float* rsk, float* part, int partBase) {
    stats_kernel<<<dim3(C / 32, 4), 256>>>(cin, muc, rsc, N, C);
    stats_kernel<<<dim3(Cc / 32, 4), 256>>>(cc, muq, rsq, N, Cc);
    stats_kernel<<<dim3(Cc / 32, 4), 256>>>(sc, muk, rsk, N, Cc);
    int nb = (int)(((size_t)4 * N * Cc + 255) / 256);
    qk_prep<<<nb, 256>>>(cc, muq, rsq, Q, N, Cc);
    qk_prep<<<nb, 256>>>(sc, muk, rsk, K, N, Cc);
    v_prep<<<dim3(N / 32, C / 32, 4), 256>>>(sty, W, N, C);
    gemm_mma<<<dim3(N / 128, N / 128, 4), 256, GSMEM>>>(
        Q, K, Cc, 0, S, nullptr, nullptr, nullptr, nullptr, C, N, nullptr, 0);
    dim3 g2(N, 4);
    if (N == 4096)      softmax_kernel<4096><<<g2, 256>>>(S, A);
    else if (N == 1024) softmax_kernel<1024><<<g2, 256>>>(S, A);
    else                softmax_kernel<256><<<g2, 256>>>(S, A);
    gemm_mma<<<dim3(2 * C / 128, N / 128, 4), 256, GSMEM>>>(
        A, W, N, 1, nullptr, cs, cin, muc, rsc, C, N, part, partBase);
}

extern "C" void kernel_launch(void* const* d_in, const int* in_sizes, int n_in,
                              void* d_out, int out_size) {
    bf16 *Q, *K, *A, *W;
    float *S, *muc, *rsc, *muq, *rsq, *muk, *rsk, *part;
    cudaGetSymbolAddress((void**)&Q, g_Qe);
    cudaGetSymbolAddress((void**)&K, g_Ke);
    cudaGetSymbolAddress((void**)&S, g_S);
    cudaGetSymbolAddress((void**)&A, g_A);
    cudaGetSymbolAddress((void**)&W, g_W);
    cudaGetSymbolAddress((void**)&muc, g_muc);
    cudaGetSymbolAddress((void**)&rsc, g_rsc);
    cudaGetSymbolAddress((void**)&muq, g_muq);
    cudaGetSymbolAddress((void**)&rsq, g_rsq);
    cudaGetSymbolAddress((void**)&muk, g_muk);
    cudaGetSymbolAddress((void**)&rsk, g_rsk);
    cudaGetSymbolAddress((void**)&part, g_part);
    cudaFuncSetAttribute(gemm_mma, cudaFuncAttributeMaxDynamicSharedMemorySize, GSMEM);

    run_scale((const float*)d_in[0], (const float*)d_in[1], (const float*)d_in[2],
              (const float*)d_in[3], (const float*)d_in[4],
              4096, 256, 448, Q, K, S, A, W, muc, rsc, muq, rsq, muk, rsk, part, 0);
    run_scale((const float*)d_in[5], (const float*)d_in[6], (const float*)d_in[7],
              (const float*)d_in[8], (const float*)d_in[9],
              1024, 512, 960, Q, K, S, A, W, muc, rsc, muq, rsq, muk, rsk, part, 512);
    run_scale((const float*)d_in[10], (const float*)d_in[11], (const float*)d_in[12],
              (const float*)d_in[13], (const float*)d_in[14],
              256, 512, 1472, Q, K, S, A, W, muc, rsc, muq, rsq, muk, rsk, part, 768);

    final_kernel<<<1, 256>>>(part, (float*)d_out);
}